// round 6
// baseline (speedup 1.0000x reference)
#include <cuda_runtime.h>

// out[b,s,e] = sum_h cs[b,s,e,h] * W[e,h] + bias[e]
// B=4, S=512, E=64, H=1024 -> ROWS = 131072 reductions over 1024 contiguous floats.
// HBM-bound streaming. R5b: persistent grid-stride warps (148*24 CTAs of 64 thr,
// warps resident for whole kernel -> no CTA churn, achieved occ ~= theoretical).
// Stride 7104 is a multiple of 64, so entity e is constant per warp: W row and
// bias hoist out of the loop and stay hot in L1. (redux.sync.add.f32 is NOT
// supported by ptxas on sm_103 — use the SHFL chain; it's hidden by co-resident
// warps anyway.)

#define E_DIM 64
#define H_DIM 1024
#define HV4   (H_DIM / 4)      // 256 float4 per row
#define WARPS_PER_BLOCK 2
#define CTAS_PER_SM 24
#define NUM_SMS 148

__device__ __forceinline__ float4 ldcs_f4(const float4* p) {
    float4 v;
    asm volatile("ld.global.cs.v4.f32 {%0,%1,%2,%3}, [%4];"
                 : "=f"(v.x), "=f"(v.y), "=f"(v.z), "=f"(v.w)
                 : "l"(p));
    return v;
}

__global__ __launch_bounds__(WARPS_PER_BLOCK * 32, CTAS_PER_SM)
void Cell_to_Entity_78735340470739_kernel(
    const float4* __restrict__ cs,    // [ROWS, HV4]
    const float4* __restrict__ W,     // [E, HV4]
    const float*  __restrict__ bias,  // [E]
    float*        __restrict__ out,   // [ROWS]
    int rows)
{
    const int lane = threadIdx.x & 31;
    const int gw   = blockIdx.x * WARPS_PER_BLOCK + (threadIdx.x >> 5);
    const int total_warps = gridDim.x * WARPS_PER_BLOCK;   // 7104, multiple of 64

    // e is invariant across the grid-stride loop (stride % 64 == 0)
    const int e = gw & (E_DIM - 1);
    const float4* __restrict__ w = W + (size_t)e * HV4;
    const float be = __ldg(&bias[e]);

    for (int row = gw; row < rows; row += total_warps) {
        const float4* __restrict__ x = cs + (size_t)row * HV4;

        float acc = 0.0f;
#pragma unroll
        for (int i = 0; i < 8; ++i) {
            const int idx = lane + 32 * i;
            float4 a = ldcs_f4(&x[idx]);   // streaming, evict-first
            float4 b = __ldg(&w[idx]);     // pinned in L1 (same row every iter)
            acc += a.x * b.x + a.y * b.y + a.z * b.z + a.w * b.w;
        }

        // warp reduction (hidden by co-resident warps' loads)
#pragma unroll
        for (int off = 16; off > 0; off >>= 1)
            acc += __shfl_xor_sync(0xffffffffu, acc, off);

        if (lane == 0)
            out[row] = acc + be;
    }
}

extern "C" void kernel_launch(void* const* d_in, const int* in_sizes, int n_in,
                              void* d_out, int out_size)
{
    const float4* cs   = (const float4*)d_in[0];   // [B,S,E,H] float32
    const float4* W    = (const float4*)d_in[1];   // [E,H]     float32
    const float*  bias = (const float*)d_in[2];    // [E]       float32
    float*        out  = (float*)d_out;            // [B,S,E]   float32

    const int rows   = out_size;                   // 131072
    const int blocks = NUM_SMS * CTAS_PER_SM;      // 3552 persistent CTAs

    Cell_to_Entity_78735340470739_kernel<<<blocks, WARPS_PER_BLOCK * 32>>>(cs, W, bias, out, rows);
}

// round 7
// speedup vs baseline: 1.1270x; 1.1270x over previous
#include <cuda_runtime.h>

// out[b,s,e] = sum_h cs[b,s,e,h] * W[e,h] + bias[e]
// B=4, S=512, E=64, H=1024 -> ROWS = 131072 reductions over 1024 contiguous floats.
// HBM-bound streaming. R6 = R4 shape (one warp per row, fresh warp per row —
// persistent/paired variants both regressed: per-warp serialization points cost
// more than CTA churn). Changes vs R4:
//   - all 8 streaming loads batched into regs BEFORE W loads (pin MLP_p1=8)
//   - 4 partial accumulators (short FFMA chains, earlier slot retirement)
//   - __launch_bounds__(64, 24) pins the 42-reg / 24-CTA/SM operating point

#define E_DIM 64
#define H_DIM 1024
#define HV4   (H_DIM / 4)      // 256 float4 per row
#define WARPS_PER_BLOCK 2

__device__ __forceinline__ float4 ldcs_f4(const float4* p) {
    float4 v;
    asm volatile("ld.global.cs.v4.f32 {%0,%1,%2,%3}, [%4];"
                 : "=f"(v.x), "=f"(v.y), "=f"(v.z), "=f"(v.w)
                 : "l"(p));
    return v;
}

__global__ __launch_bounds__(WARPS_PER_BLOCK * 32, 24)
void Cell_to_Entity_78735340470739_kernel(
    const float4* __restrict__ cs,    // [ROWS, HV4]
    const float4* __restrict__ W,     // [E, HV4]
    const float*  __restrict__ bias,  // [E]
    float*        __restrict__ out)   // [ROWS]
{
    const int warp = threadIdx.x >> 5;
    const int lane = threadIdx.x & 31;
    const int row  = blockIdx.x * WARPS_PER_BLOCK + warp;

    const int e = row & (E_DIM - 1);

    const float4* __restrict__ x = cs + (size_t)row * HV4;
    const float4* __restrict__ w = W  + (size_t)e   * HV4;

    // Front-batch the 8 streaming loads: guarantees 8 independent LDG.128
    // in flight on the DRAM stream before anything else issues.
    float4 a[8];
#pragma unroll
    for (int i = 0; i < 8; ++i)
        a[i] = ldcs_f4(&x[lane + 32 * i]);

    // W loads are L1/L2 hits; consume into 4 independent partial sums.
    float p0 = 0.f, p1 = 0.f, p2 = 0.f, p3 = 0.f;
#pragma unroll
    for (int i = 0; i < 8; i += 4) {
        float4 b0 = __ldg(&w[lane + 32 * (i + 0)]);
        float4 b1 = __ldg(&w[lane + 32 * (i + 1)]);
        float4 b2 = __ldg(&w[lane + 32 * (i + 2)]);
        float4 b3 = __ldg(&w[lane + 32 * (i + 3)]);
        p0 += a[i+0].x * b0.x + a[i+0].y * b0.y + a[i+0].z * b0.z + a[i+0].w * b0.w;
        p1 += a[i+1].x * b1.x + a[i+1].y * b1.y + a[i+1].z * b1.z + a[i+1].w * b1.w;
        p2 += a[i+2].x * b2.x + a[i+2].y * b2.y + a[i+2].z * b2.z + a[i+2].w * b2.w;
        p3 += a[i+3].x * b3.x + a[i+3].y * b3.y + a[i+3].z * b3.z + a[i+3].w * b3.w;
    }
    float acc = (p0 + p1) + (p2 + p3);

    // warp reduction
#pragma unroll
    for (int off = 16; off > 0; off >>= 1)
        acc += __shfl_xor_sync(0xffffffffu, acc, off);

    if (lane == 0)
        out[row] = acc + __ldg(&bias[e]);
}

extern "C" void kernel_launch(void* const* d_in, const int* in_sizes, int n_in,
                              void* d_out, int out_size)
{
    const float4* cs   = (const float4*)d_in[0];   // [B,S,E,H] float32
    const float4* W    = (const float4*)d_in[1];   // [E,H]     float32
    const float*  bias = (const float*)d_in[2];    // [E]       float32
    float*        out  = (float*)d_out;            // [B,S,E]   float32

    const int rows   = out_size;                   // B*S*E = 131072
    const int blocks = rows / WARPS_PER_BLOCK;     // 65536

    Cell_to_Entity_78735340470739_kernel<<<blocks, WARPS_PER_BLOCK * 32>>>(cs, W, bias, out);
}

// round 8
// speedup vs baseline: 1.1349x; 1.0070x over previous
#include <cuda_runtime.h>

// out[b,s,e] = sum_h cs[b,s,e,h] * W[e,h] + bias[e]
// B=4, S=512, E=64, H=1024 -> ROWS = 131072 reductions over 1024 contiguous floats.
// FINAL (R7 = R4 consolidated): pure HBM-streaming kernel at the B300 practical
// ceiling (~6.8 TB/s, 85-86% of spec; remaining gap is refresh/channel-hash,
// not software-addressable — verified by 3 structural variants in R3/R5/R6).
// Shape: one warp per row, fresh warp per row, 64-thread CTAs, .cs streaming
// loads for the one-pass cs tensor, __ldg for the L1-resident W row.
// Micro-edits vs R4: bias load hoisted ahead of the SHFL chain; output stored
// with st.global.cs (never re-read).

#define E_DIM 64
#define H_DIM 1024
#define HV4   (H_DIM / 4)      // 256 float4 per row
#define WARPS_PER_BLOCK 2

__device__ __forceinline__ float4 ldcs_f4(const float4* p) {
    float4 v;
    asm volatile("ld.global.cs.v4.f32 {%0,%1,%2,%3}, [%4];"
                 : "=f"(v.x), "=f"(v.y), "=f"(v.z), "=f"(v.w)
                 : "l"(p));
    return v;
}

__device__ __forceinline__ void stcs_f32(float* p, float v) {
    asm volatile("st.global.cs.f32 [%0], %1;" :: "l"(p), "f"(v) : "memory");
}

__global__ __launch_bounds__(WARPS_PER_BLOCK * 32)
void Cell_to_Entity_78735340470739_kernel(
    const float4* __restrict__ cs,    // [ROWS, HV4]
    const float4* __restrict__ W,     // [E, HV4]
    const float*  __restrict__ bias,  // [E]
    float*        __restrict__ out)   // [ROWS]
{
    const int warp = threadIdx.x >> 5;
    const int lane = threadIdx.x & 31;
    const int row  = blockIdx.x * WARPS_PER_BLOCK + warp;

    const int e = row & (E_DIM - 1);

    const float4* __restrict__ x = cs + (size_t)row * HV4;
    const float4* __restrict__ w = W  + (size_t)e   * HV4;

    float acc = 0.0f;
#pragma unroll
    for (int i = 0; i < 8; ++i) {
        const int idx = lane + 32 * i;
        float4 a = ldcs_f4(&x[idx]);   // streaming, evict-first: one-pass data
        float4 b = __ldg(&w[idx]);     // hot in L1/L2 (256 KiB total W)
        acc += a.x * b.x + a.y * b.y + a.z * b.z + a.w * b.w;
    }

    // bias fetched before the reduction chain so it overlaps the shuffles
    const float be = __ldg(&bias[e]);

    // warp reduction
#pragma unroll
    for (int off = 16; off > 0; off >>= 1)
        acc += __shfl_xor_sync(0xffffffffu, acc, off);

    if (lane == 0)
        stcs_f32(&out[row], acc + be);
}

extern "C" void kernel_launch(void* const* d_in, const int* in_sizes, int n_in,
                              void* d_out, int out_size)
{
    const float4* cs   = (const float4*)d_in[0];   // [B,S,E,H] float32
    const float4* W    = (const float4*)d_in[1];   // [E,H]     float32
    const float*  bias = (const float*)d_in[2];    // [E]       float32
    float*        out  = (float*)d_out;            // [B,S,E]   float32

    const int rows   = out_size;                   // B*S*E = 131072
    const int blocks = rows / WARPS_PER_BLOCK;     // 65536

    Cell_to_Entity_78735340470739_kernel<<<blocks, WARPS_PER_BLOCK * 32>>>(cs, W, bias, out);
}